// round 4
// baseline (speedup 1.0000x reference)
#include <cuda_runtime.h>

// Problem constants
#define DIMC 192
#define RR   48            // DIM/RED
#define BB   4
#define HH   256
#define WW   256
#define PLANE (HH*WW)      // 65536
#define NPLANES (BB*DIMC)  // 768
#define EPS_BN 1e-5f

// Scratch (no allocations allowed)
__device__ float g_partial[NPLANES * 4];   // per-quarter-plane sums
__device__ float g_t[BB * RR];             // post-BN-ReLU hidden
__device__ float g_wt[NPLANES * 4];        // 4 surviving masked taps per plane

// ---------------------------------------------------------------------------
// Kernel 1: partial sums for channel-wise mean. 3072 blocks x 256 threads.
// Each block reduces one quarter (16384 floats) of one plane.
// ---------------------------------------------------------------------------
__global__ void pool_partial_kernel(const float* __restrict__ x) {
    int bid = blockIdx.x;                  // [0, 3072)
    int plane = bid >> 2;
    int quarter = bid & 3;
    const float4* p = reinterpret_cast<const float4*>(
        x + (size_t)plane * PLANE + quarter * (PLANE / 4));
    float s = 0.f;
    #pragma unroll
    for (int j = 0; j < 16; ++j) {
        float4 v = p[threadIdx.x + j * 256];
        s += (v.x + v.y) + (v.z + v.w);
    }
    // warp reduce
    #pragma unroll
    for (int o = 16; o > 0; o >>= 1) s += __shfl_down_sync(0xffffffffu, s, o);
    __shared__ float sm[8];
    int lane = threadIdx.x & 31, w = threadIdx.x >> 5;
    if (lane == 0) sm[w] = s;
    __syncthreads();
    if (threadIdx.x < 8) {
        float v = sm[threadIdx.x];
        #pragma unroll
        for (int o = 4; o > 0; o >>= 1) v += __shfl_down_sync(0xffu, v, o);
        if (threadIdx.x == 0) g_partial[bid] = v;
    }
}

// ---------------------------------------------------------------------------
// Kernel 2: t = relu(BN(pooled @ w1^T)). Single block, 256 threads.
// ---------------------------------------------------------------------------
__global__ void compute_t_kernel(const float* __restrict__ w1,
                                 const float* __restrict__ gamma,
                                 const float* __restrict__ beta,
                                 const float* __restrict__ rmean,
                                 const float* __restrict__ rvar) {
    __shared__ float sp[NPLANES];
    for (int j = threadIdx.x; j < NPLANES; j += 256) {
        sp[j] = (g_partial[4*j] + g_partial[4*j+1] + g_partial[4*j+2] + g_partial[4*j+3])
                * (1.f / (float)PLANE);
    }
    __syncthreads();
    if (threadIdx.x < BB * RR) {
        int b = threadIdx.x / RR;
        int r = threadIdx.x % RR;
        const float* pb = &sp[b * DIMC];
        const float* wr = &w1[r * DIMC];
        float acc = 0.f;
        #pragma unroll 4
        for (int k = 0; k < DIMC; ++k) acc = fmaf(pb[k], wr[k], acc);
        acc = gamma[r] * (acc - rmean[r]) * rsqrtf(rvar[r] + EPS_BN) + beta[r];
        g_t[threadIdx.x] = fmaxf(acc, 0.f);
    }
}

// ---------------------------------------------------------------------------
// Kernel 3: masked dynamic weights. Mask 'A' keeps taps k=0..3 of the 3x3
// (row0 cols 0..2, row1 col0). 12 blocks x 256 threads -> 3072 weights.
// g_wt layout: [plane=b*192+c][k].
// ---------------------------------------------------------------------------
__global__ void compute_wt_kernel(const float* __restrict__ w2,
                                  const float* __restrict__ b2) {
    __shared__ float st[BB * RR];
    if (threadIdx.x < BB * RR) st[threadIdx.x] = g_t[threadIdx.x];
    __syncthreads();
    int idx = blockIdx.x * 256 + threadIdx.x;   // [0, 3072)
    int b = idx / (DIMC * 4);
    int rem = idx % (DIMC * 4);
    int c = rem >> 2;
    int k = rem & 3;
    int row = c * 9 + k;                         // w2 row index (K*K=9 taps)
    const float* wr = &w2[row * RR];
    const float* tb = &st[b * RR];
    float acc = b2[row];
    #pragma unroll
    for (int r = 0; r < RR; ++r) acc = fmaf(tb[r], wr[r], acc);
    g_wt[idx] = acc;
}

// ---------------------------------------------------------------------------
// Kernel 4: masked depthwise conv (4 taps) + bias.
// out[y][x] = w0*X[y-1][x-1] + w1*X[y-1][x] + w2*X[y-1][x+1] + w3*X[y][x-1] + bias
// grid: 768 planes * 64 row-groups; block 256 threads = 64 x-threads x 4 rows,
// each thread produces a float4 (4 consecutive x).
// ---------------------------------------------------------------------------
__global__ void __launch_bounds__(256, 8)
conv_kernel(const float* __restrict__ x,
            const float* __restrict__ bias,
            float* __restrict__ out) {
    int plane = blockIdx.x >> 6;
    int rg    = blockIdx.x & 63;
    int ty = threadIdx.x >> 6;
    int tx = threadIdx.x & 63;
    int y  = rg * 4 + ty;
    int x0 = tx << 2;

    const float* Xp  = x + (size_t)plane * PLANE;
    const float* cur = Xp + y * WW;

    float4 c4 = *reinterpret_cast<const float4*>(cur + x0);
    float cl  = (x0 > 0) ? cur[x0 - 1] : 0.f;

    float4 a4 = make_float4(0.f, 0.f, 0.f, 0.f);
    float al = 0.f, ar = 0.f;
    if (y > 0) {
        const float* ab = cur - WW;
        a4 = *reinterpret_cast<const float4*>(ab + x0);
        al = (x0 > 0)   ? ab[x0 - 1] : 0.f;
        ar = (x0 < WW-4) ? ab[x0 + 4] : 0.f;
    }

    const float4 w = *reinterpret_cast<const float4*>(g_wt + plane * 4);
    float bv = __ldg(&bias[plane % DIMC]);

    float4 o;
    o.x = fmaf(w.x, al,   fmaf(w.y, a4.x, fmaf(w.z, a4.y, fmaf(w.w, cl,   bv))));
    o.y = fmaf(w.x, a4.x, fmaf(w.y, a4.y, fmaf(w.z, a4.z, fmaf(w.w, c4.x, bv))));
    o.z = fmaf(w.x, a4.y, fmaf(w.y, a4.z, fmaf(w.z, a4.w, fmaf(w.w, c4.y, bv))));
    o.w = fmaf(w.x, a4.z, fmaf(w.y, a4.w, fmaf(w.z, ar,   fmaf(w.w, c4.z, bv))));

    *reinterpret_cast<float4*>(out + (size_t)plane * PLANE + y * WW + x0) = o;
}

// ---------------------------------------------------------------------------
extern "C" void kernel_launch(void* const* d_in, const int* in_sizes, int n_in,
                              void* d_out, int out_size) {
    const float* x     = (const float*)d_in[0];
    const float* w1    = (const float*)d_in[1];
    const float* gamma = (const float*)d_in[2];
    const float* beta  = (const float*)d_in[3];
    const float* rmean = (const float*)d_in[4];
    const float* rvar  = (const float*)d_in[5];
    const float* w2    = (const float*)d_in[6];
    const float* b2    = (const float*)d_in[7];
    const float* bias  = (const float*)d_in[8];
    float* out = (float*)d_out;

    pool_partial_kernel<<<NPLANES * 4, 256>>>(x);
    compute_t_kernel<<<1, 256>>>(w1, gamma, beta, rmean, rvar);
    compute_wt_kernel<<<12, 256>>>(w2, b2);
    conv_kernel<<<NPLANES * 64, 256>>>(x, bias, out);
}